// round 8
// baseline (speedup 1.0000x reference)
#include <cuda_runtime.h>
#include <cuda_bf16.h>
#include <cstdint>
#include <math.h>

#define EMAX   250000
#define DEDGE  128
#define DTRI   64

// fp32 intermediates
static __device__ __align__(16) float g_T  [EMAX * DTRI];
static __device__ __align__(16) float g_Z  [EMAX * DEDGE];
// bf16 hi/lo pre-split activations
static __device__ __align__(16) __nv_bfloat16 g_msth[EMAX * DEDGE];
static __device__ __align__(16) __nv_bfloat16 g_mstl[EMAX * DEDGE];
static __device__ __align__(16) __nv_bfloat16 g_Xh  [EMAX * DTRI];
static __device__ __align__(16) __nv_bfloat16 g_Xl  [EMAX * DTRI];
static __device__ __align__(16) __nv_bfloat16 g_Yh  [EMAX * DEDGE];
static __device__ __align__(16) __nv_bfloat16 g_Yl  [EMAX * DEDGE];
// bf16 hi/lo transposed weights [N][K]
static __device__ __align__(16) __nv_bfloat16 g_Wmrh [128 * 128], g_Wmrl [128 * 128];
static __device__ __align__(16) __nv_bfloat16 g_Wmch [64 * 128],  g_Wmcl [64 * 128];
static __device__ __align__(16) __nv_bfloat16 g_Wdh  [128 * 64],  g_Wdl  [128 * 64];
static __device__ __align__(16) __nv_bfloat16 g_Wsth [128 * 128], g_Wstl [128 * 128];
static __device__ __align__(16) __nv_bfloat16 g_Wtsh [128 * 128], g_Wtsl [128 * 128];

#define INV_SQRT_2  0.70710678118654752440f
#define INV_SQRT_NB 0.35355339059327376220f

__device__ __forceinline__ float silu_f(float x) {
    return x / (1.0f + __expf(-x));
}
__device__ __forceinline__ uint32_t smem_u32(const void* p) {
    uint32_t a;
    asm("{ .reg .u64 t; cvta.to.shared.u64 t, %1; cvt.u32.u64 %0, t; }" : "=r"(a) : "l"(p));
    return a;
}
__device__ __forceinline__ void cp_async16(uint32_t dst, const void* src, bool v) {
    int sz = v ? 16 : 0;
    asm volatile("cp.async.cg.shared.global [%0], [%1], 16, %2;"
                 :: "r"(dst), "l"(src), "r"(sz));
}
#define CP_COMMIT() asm volatile("cp.async.commit_group;" ::: "memory")
template<int n> __device__ __forceinline__ void cp_wait() {
    asm volatile("cp.async.wait_group %0;" :: "n"(n) : "memory");
}
__device__ __forceinline__ void ldsm4(uint32_t addr, uint32_t& r0, uint32_t& r1,
                                      uint32_t& r2, uint32_t& r3) {
    asm volatile("ldmatrix.sync.aligned.m8n8.x4.shared.b16 {%0,%1,%2,%3}, [%4];"
                 : "=r"(r0), "=r"(r1), "=r"(r2), "=r"(r3) : "r"(addr));
}
__device__ __forceinline__ void mma_bf16(float* c, const uint32_t* a,
                                         uint32_t b0, uint32_t b1) {
    asm volatile(
        "mma.sync.aligned.m16n8k16.row.col.f32.bf16.bf16.f32 "
        "{%0,%1,%2,%3}, {%4,%5,%6,%7}, {%8,%9}, {%0,%1,%2,%3};"
        : "+f"(c[0]), "+f"(c[1]), "+f"(c[2]), "+f"(c[3])
        : "r"(a[0]), "r"(a[1]), "r"(a[2]), "r"(a[3]), "r"(b0), "r"(b1));
}
__device__ __forceinline__ void split1(float v, __nv_bfloat16& h, __nv_bfloat16& l) {
    h = __float2bfloat16(v);
    l = __float2bfloat16(v - __bfloat162float(h));
}
__device__ __forceinline__ uint32_t pack2(__nv_bfloat16 a, __nv_bfloat16 b) {
    __nv_bfloat162 p; p.x = a; p.y = b;
    return *(uint32_t*)&p;
}
// split a float2 into packed hi u32 and packed lo u32
__device__ __forceinline__ void split_pack(float2 v, uint32_t& H, uint32_t& L) {
    __nv_bfloat16 hx, lx, hy, ly;
    split1(v.x, hx, lx); split1(v.y, hy, ly);
    H = pack2(hx, hy); L = pack2(lx, ly);
}

// ---------------- setup split kernels ----------------
__global__ void split_rows(const float* __restrict__ src,
                           __nv_bfloat16* __restrict__ dh,
                           __nv_bfloat16* __restrict__ dl, int n2)
{
    int i = blockIdx.x * blockDim.x + threadIdx.x;
    if (i >= n2) return;
    float2 v = ((const float2*)src)[i];
    uint32_t H, L;
    split_pack(v, H, L);
    ((uint32_t*)dh)[i] = H;
    ((uint32_t*)dl)[i] = L;
}

// W[K][N] fp32 -> Wt[N][K] bf16 hi/lo
__global__ void split_w_t(const float* __restrict__ src,
                          __nv_bfloat16* __restrict__ dh,
                          __nv_bfloat16* __restrict__ dl, int K, int N)
{
    int i = blockIdx.x * blockDim.x + threadIdx.x;
    if (i >= K * N) return;
    int k = i / N, n = i % N;
    __nv_bfloat16 h, l;
    split1(src[i], h, l);
    dh[n * K + k] = h;
    dl[n * K + k] = l;
}

#define EPI_NONE 0
#define EPI_SILU 1
#define EPI_FINAL 3

// ---------------- standalone GEMM ----------------
template<int K, int N, int EPI>
__global__ void __launch_bounds__(256, 2)
gemm_std(const __nv_bfloat16* __restrict__ Ah, const __nv_bfloat16* __restrict__ Al,
         const __nv_bfloat16* __restrict__ Bh, const __nv_bfloat16* __restrict__ Bl,
         float* __restrict__ outf,
         const float* __restrict__ Zg, const int* __restrict__ swp, int M)
{
    constexpr int NT    = N / 16;
    constexpr int NPAIR = NT / 2;
    constexpr int NCH   = (K + 31) / 32;
    constexpr int ST    = 40;
    constexpr uint32_t OFF_AL = 128 * ST * 2;
    constexpr uint32_t OFF_BH = 2 * 128 * ST * 2;
    constexpr uint32_t OFF_BL = OFF_BH + N * ST * 2;
    constexpr uint32_t SSZ    = OFF_BH + 2 * N * ST * 2;

    extern __shared__ __align__(16) char smu[];
    const uint32_t sbase = smem_u32(smu);

    const int tid  = threadIdx.x;
    const int warp = tid >> 5, lane = tid & 31;
    const int g = lane >> 2, t = lane & 3;
    const int warpM = warp & 3, warpN = warp >> 2;
    const int m0 = warpM * 32;
    const int n0 = warpN * (N / 2);
    const int blockRow = blockIdx.x * 128;

    const int lr  = lane & 7;
    const int rowA_base = m0 + lr + ((lane >> 3) & 1) * 8;
    const int kA_off    = (lane >> 4) * 8;
    const int rowB_base = n0 + lr + (lane >> 4) * 8;
    const int kB_off    = ((lane >> 3) & 1) * 8;

    float acc[2][NT][4];
    #pragma unroll
    for (int mt = 0; mt < 2; mt++)
        #pragma unroll
        for (int nt = 0; nt < NT; nt++)
            #pragma unroll
            for (int j = 0; j < 4; j++) acc[mt][nt][j] = 0.0f;

    auto load_chunk = [&](int kb, int stage) {
        const int k0 = kb * 32;
        const uint32_t sb = sbase + (uint32_t)stage * SSZ;
        #pragma unroll
        for (int j = 0; j < 2; j++) {
            int gg = tid + j * 256;
            int row = gg >> 2, q = gg & 3;
            bool v = (blockRow + row < M) && (k0 + q * 8 < K);
            size_t so = (size_t)(blockRow + row) * K + k0 + q * 8;
            uint32_t d = sb + (uint32_t)(row * ST + q * 8) * 2;
            cp_async16(d, v ? (Ah + so) : Ah, v);
            cp_async16(d + OFF_AL, v ? (Al + so) : Al, v);
        }
        #pragma unroll
        for (int j = 0; j < (N * 4) / 256; j++) {
            int gg = tid + j * 256;
            int n = gg >> 2, q = gg & 3;
            bool v = (k0 + q * 8 < K);
            size_t so = (size_t)n * K + k0 + q * 8;
            uint32_t d = sb + OFF_BH + (uint32_t)(n * ST + q * 8) * 2;
            cp_async16(d, v ? (Bh + so) : Bh, v);
            cp_async16(d + (uint32_t)(N * ST * 2), v ? (Bl + so) : Bl, v);
        }
        CP_COMMIT();
    };

    load_chunk(0, 0);
    for (int kb = 0; kb < NCH; kb++) {
        if (kb + 1 < NCH) { load_chunk(kb + 1, (kb + 1) & 1); cp_wait<1>(); }
        else              { cp_wait<0>(); }
        __syncthreads();

        const uint32_t sb = sbase + (uint32_t)(kb & 1) * SSZ;
        #pragma unroll
        for (int ks = 0; ks < 2; ks++) {
            uint32_t ah[2][4], al[2][4];
            #pragma unroll
            for (int mt = 0; mt < 2; mt++) {
                uint32_t ea = (uint32_t)((rowA_base + mt * 16) * ST + ks * 16 + kA_off) * 2;
                ldsm4(sb + ea,          ah[mt][0], ah[mt][1], ah[mt][2], ah[mt][3]);
                ldsm4(sb + OFF_AL + ea, al[mt][0], al[mt][1], al[mt][2], al[mt][3]);
            }
            #pragma unroll
            for (int p = 0; p < NPAIR; p++) {
                uint32_t eb = (uint32_t)((rowB_base + p * 16) * ST + ks * 16 + kB_off) * 2;
                uint32_t bh0, bh1, bh2, bh3, bl0, bl1, bl2, bl3;
                ldsm4(sb + OFF_BH + eb, bh0, bh1, bh2, bh3);
                ldsm4(sb + OFF_BL + eb, bl0, bl1, bl2, bl3);
                #pragma unroll
                for (int mt = 0; mt < 2; mt++) {
                    float* c0 = acc[mt][2 * p];
                    float* c1 = acc[mt][2 * p + 1];
                    mma_bf16(c0, ah[mt], bh0, bh1);
                    mma_bf16(c0, ah[mt], bl0, bl1);
                    mma_bf16(c0, al[mt], bh0, bh1);
                    mma_bf16(c1, ah[mt], bh2, bh3);
                    mma_bf16(c1, ah[mt], bl2, bl3);
                    mma_bf16(c1, al[mt], bh2, bh3);
                }
            }
        }
        __syncthreads();
    }

    #pragma unroll
    for (int mt = 0; mt < 2; mt++) {
        #pragma unroll
        for (int half = 0; half < 2; half++) {
            int r = blockRow + m0 + mt * 16 + g + half * 8;
            if (r >= M) continue;
            int s = 0;
            if (EPI == EPI_FINAL) s = swp[r];
            #pragma unroll
            for (int nt = 0; nt < NT; nt++) {
                int cc = n0 + nt * 8 + 2 * t;
                float v0 = acc[mt][nt][half * 2 + 0];
                float v1 = acc[mt][nt][half * 2 + 1];
                if (EPI != EPI_NONE) { v0 = silu_f(v0); v1 = silu_f(v1); }
                if (EPI == EPI_FINAL) {
                    float2 z = *(const float2*)(Zg + (size_t)s * N + cc);
                    v0 = (v0 + z.x) * INV_SQRT_2;
                    v1 = (v1 + z.y) * INV_SQRT_2;
                }
                float2 o; o.x = v0; o.y = v1;
                *(float2*)(outf + (size_t)r * N + cc) = o;
            }
        }
    }
}

// ---------------- chained GEMM ----------------
// Phase1: P = silu(A @ B1^T) [* R(rbf@Wrbf, computed in fp32 in epilogue)]
//         P -> smem slabs bf16 hi/lo (and optionally gmem Yh/Yl)
// Phase2: out2 = silu(P @ B2^T)
template<int K1, int N2, bool HAS_R, bool STORE_Y>
__global__ void __launch_bounds__(256, 2)
gemm_chain(const __nv_bfloat16* __restrict__ Ah, const __nv_bfloat16* __restrict__ Al,
           const __nv_bfloat16* __restrict__ B1h, const __nv_bfloat16* __restrict__ B1l,
           const float* __restrict__ rbf_g, const float* __restrict__ Wrbf_g,
           const __nv_bfloat16* __restrict__ B2h, const __nv_bfloat16* __restrict__ B2l,
           float* __restrict__ out2,
           __nv_bfloat16* __restrict__ Yh, __nv_bfloat16* __restrict__ Yl, int M)
{
    constexpr int N1  = 128;
    constexpr int ST  = 40;
    constexpr int NCH1 = (K1 + 31) / 32;
    constexpr uint32_t OFF_AL = 128 * ST * 2;
    constexpr uint32_t OFF_BH = 2 * 128 * ST * 2;
    constexpr uint32_t SSZ    = OFF_BH + 2 * N1 * ST * 2;   // 40960
    constexpr uint32_t SLAB   = 128 * ST * 2 * 2;           // 20480
    constexpr uint32_t B2OFF  = 2 * SSZ;                    // 81920
    constexpr uint32_t WOFF   = B2OFF + 2u * N2 * ST * 2;   // after B2 buffer
    constexpr int NT2   = N2 / 16;
    constexpr int NPAIR2 = NT2 / 2;

    extern __shared__ __align__(16) char smu[];
    const uint32_t sbase = smem_u32(smu);

    const int tid  = threadIdx.x;
    const int warp = tid >> 5, lane = tid & 31;
    const int g = lane >> 2, t = lane & 3;
    const int warpM = warp & 3, warpN = warp >> 2;
    const int m0 = warpM * 32;
    const int n0 = warpN * 64;
    const int n0b = warpN * (N2 / 2);
    const int blockRow = blockIdx.x * 128;

    const int lr  = lane & 7;
    const int rowA_base = m0 + lr + ((lane >> 3) & 1) * 8;
    const int kA_off    = (lane >> 4) * 8;
    const int rowB_base = n0 + lr + (lane >> 4) * 8;
    const int rowB2_base = n0b + lr + (lane >> 4) * 8;
    const int kB_off    = ((lane >> 3) & 1) * 8;

    // ======== phase 1 ========
    {
        float acc[2][8][4];
        #pragma unroll
        for (int mt = 0; mt < 2; mt++)
            #pragma unroll
            for (int nt = 0; nt < 8; nt++)
                #pragma unroll
                for (int j = 0; j < 4; j++) acc[mt][nt][j] = 0.0f;

        auto load_chunk = [&](int kb, int stage) {
            const int k0 = kb * 32;
            const uint32_t sb = sbase + (uint32_t)stage * SSZ;
            #pragma unroll
            for (int j = 0; j < 2; j++) {
                int gg = tid + j * 256;
                int row = gg >> 2, q = gg & 3;
                bool v = (blockRow + row < M) && (k0 + q * 8 < K1);
                size_t so = (size_t)(blockRow + row) * K1 + k0 + q * 8;
                uint32_t d = sb + (uint32_t)(row * ST + q * 8) * 2;
                cp_async16(d, v ? (Ah + so) : Ah, v);
                cp_async16(d + OFF_AL, v ? (Al + so) : Al, v);
            }
            #pragma unroll
            for (int j = 0; j < 2; j++) {
                int gg = tid + j * 256;
                int n = gg >> 2, q = gg & 3;
                bool v = (k0 + q * 8 < K1);
                size_t so = (size_t)n * K1 + k0 + q * 8;
                uint32_t d = sb + OFF_BH + (uint32_t)(n * ST + q * 8) * 2;
                cp_async16(d, v ? (B1h + so) : B1h, v);
                cp_async16(d + (uint32_t)(N1 * ST * 2), v ? (B1l + so) : B1l, v);
            }
            CP_COMMIT();
        };

        // Wrbf fp32 (16x128 = 8 KB) -> smem, joins first commit group
        if (HAS_R) {
            #pragma unroll
            for (int j = 0; j < 2; j++) {
                int q = tid + j * 256;
                cp_async16(sbase + WOFF + (uint32_t)q * 16, Wrbf_g + q * 4, true);
            }
        }
        load_chunk(0, 0);
        for (int kb = 0; kb < NCH1; kb++) {
            if (kb + 1 < NCH1) { load_chunk(kb + 1, (kb + 1) & 1); cp_wait<1>(); }
            else               { cp_wait<0>(); }
            __syncthreads();

            const uint32_t sb = sbase + (uint32_t)(kb & 1) * SSZ;
            #pragma unroll
            for (int ks = 0; ks < 2; ks++) {
                uint32_t ah[2][4], al[2][4];
                #pragma unroll
                for (int mt = 0; mt < 2; mt++) {
                    uint32_t ea = (uint32_t)((rowA_base + mt * 16) * ST + ks * 16 + kA_off) * 2;
                    ldsm4(sb + ea,          ah[mt][0], ah[mt][1], ah[mt][2], ah[mt][3]);
                    ldsm4(sb + OFF_AL + ea, al[mt][0], al[mt][1], al[mt][2], al[mt][3]);
                }
                #pragma unroll
                for (int p = 0; p < 4; p++) {
                    uint32_t eb = (uint32_t)((rowB_base + p * 16) * ST + ks * 16 + kB_off) * 2;
                    uint32_t bh0, bh1, bh2, bh3, bl0, bl1, bl2, bl3;
                    ldsm4(sb + OFF_BH + eb, bh0, bh1, bh2, bh3);
                    ldsm4(sb + OFF_BH + (uint32_t)(N1 * ST * 2) + eb, bl0, bl1, bl2, bl3);
                    #pragma unroll
                    for (int mt = 0; mt < 2; mt++) {
                        float* c0 = acc[mt][2 * p];
                        float* c1 = acc[mt][2 * p + 1];
                        mma_bf16(c0, ah[mt], bh0, bh1);
                        mma_bf16(c0, ah[mt], bl0, bl1);
                        mma_bf16(c0, al[mt], bh0, bh1);
                        mma_bf16(c1, ah[mt], bh2, bh3);
                        mma_bf16(c1, ah[mt], bl2, bl3);
                        mma_bf16(c1, al[mt], bh2, bh3);
                    }
                }
            }
            __syncthreads();
        }

        // epilogue 1: silu, [* R computed fp32 from rbf @ Wrbf], split -> slabs (+ gmem Y)
        const float2* Wsm2 = (const float2*)(smu + WOFF);
        #pragma unroll
        for (int mt = 0; mt < 2; mt++) {
            int row0 = m0 + mt * 16 + g;
            int row1 = row0 + 8;
            int gr0 = blockRow + row0, gr1 = blockRow + row1;
            float rb0[16], rb1[16];
            if (HAS_R) {
                #pragma unroll
                for (int q = 0; q < 4; q++) {
                    float4 v0 = make_float4(0.f, 0.f, 0.f, 0.f);
                    float4 v1 = make_float4(0.f, 0.f, 0.f, 0.f);
                    if (gr0 < M) v0 = *(const float4*)(rbf_g + (size_t)gr0 * 16 + q * 4);
                    if (gr1 < M) v1 = *(const float4*)(rbf_g + (size_t)gr1 * 16 + q * 4);
                    rb0[q * 4 + 0] = v0.x; rb0[q * 4 + 1] = v0.y;
                    rb0[q * 4 + 2] = v0.z; rb0[q * 4 + 3] = v0.w;
                    rb1[q * 4 + 0] = v1.x; rb1[q * 4 + 1] = v1.y;
                    rb1[q * 4 + 2] = v1.z; rb1[q * 4 + 3] = v1.w;
                }
            }
            #pragma unroll
            for (int nt = 0; nt < 8; nt++) {
                int cc = n0 + nt * 8 + 2 * t;
                float r00 = 1.f, r01 = 1.f, r10 = 1.f, r11 = 1.f;
                if (HAS_R) {
                    r00 = r01 = r10 = r11 = 0.f;
                    #pragma unroll
                    for (int k = 0; k < 16; k++) {
                        float2 w = Wsm2[k * 64 + (cc >> 1)];
                        r00 = fmaf(rb0[k], w.x, r00); r01 = fmaf(rb0[k], w.y, r01);
                        r10 = fmaf(rb1[k], w.x, r10); r11 = fmaf(rb1[k], w.y, r11);
                    }
                }
                float v00 = silu_f(acc[mt][nt][0]) * r00;
                float v01 = silu_f(acc[mt][nt][1]) * r01;
                float v10 = silu_f(acc[mt][nt][2]) * r10;
                float v11 = silu_f(acc[mt][nt][3]) * r11;
                if (gr0 >= M) { v00 = 0.f; v01 = 0.f; }
                if (gr1 >= M) { v10 = 0.f; v11 = 0.f; }
                uint32_t H0, L0, H1, L1;
                split_pack(make_float2(v00, v01), H0, L0);
                split_pack(make_float2(v10, v11), H1, L1);
                uint32_t chunk = (uint32_t)(cc >> 5);
                uint32_t off0 = (uint32_t)(row0 * ST + (cc & 31)) * 2;
                uint32_t off1 = (uint32_t)(row1 * ST + (cc & 31)) * 2;
                *(uint32_t*)(smu + chunk * SLAB + off0)          = H0;
                *(uint32_t*)(smu + chunk * SLAB + OFF_AL + off0) = L0;
                *(uint32_t*)(smu + chunk * SLAB + off1)          = H1;
                *(uint32_t*)(smu + chunk * SLAB + OFF_AL + off1) = L1;
                if (STORE_Y) {
                    if (gr0 < M) {
                        *(uint32_t*)(Yh + (size_t)gr0 * N1 + cc) = H0;
                        *(uint32_t*)(Yl + (size_t)gr0 * N1 + cc) = L0;
                    }
                    if (gr1 < M) {
                        *(uint32_t*)(Yh + (size_t)gr1 * N1 + cc) = H1;
                        *(uint32_t*)(Yl + (size_t)gr1 * N1 + cc) = L1;
                    }
                }
            }
        }
        __syncthreads();
    }

    // ======== phase 2: out2 = silu(P @ B2^T), K2 = 128 ========
    {
        float acc2[2][NT2][4];
        #pragma unroll
        for (int mt = 0; mt < 2; mt++)
            #pragma unroll
            for (int nt = 0; nt < NT2; nt++)
                #pragma unroll
                for (int j = 0; j < 4; j++) acc2[mt][nt][j] = 0.0f;

        const uint32_t b2base = sbase + B2OFF;

        for (int kb = 0; kb < 4; kb++) {
            #pragma unroll
            for (int j = 0; j < (N2 * 4) / 256; j++) {
                int gg = tid + j * 256;
                int n = gg >> 2, q = gg & 3;
                size_t so = (size_t)n * 128 + kb * 32 + q * 8;
                uint32_t d = b2base + (uint32_t)(n * ST + q * 8) * 2;
                cp_async16(d, B2h + so, true);
                cp_async16(d + (uint32_t)(N2 * ST * 2), B2l + so, true);
            }
            CP_COMMIT();
            cp_wait<0>();
            __syncthreads();

            const uint32_t slab = sbase + (uint32_t)kb * SLAB;
            #pragma unroll
            for (int ks = 0; ks < 2; ks++) {
                uint32_t ah[2][4], al[2][4];
                #pragma unroll
                for (int mt = 0; mt < 2; mt++) {
                    uint32_t ea = (uint32_t)((rowA_base + mt * 16) * ST + ks * 16 + kA_off) * 2;
                    ldsm4(slab + ea,          ah[mt][0], ah[mt][1], ah[mt][2], ah[mt][3]);
                    ldsm4(slab + OFF_AL + ea, al[mt][0], al[mt][1], al[mt][2], al[mt][3]);
                }
                #pragma unroll
                for (int p = 0; p < NPAIR2; p++) {
                    uint32_t eb = (uint32_t)((rowB2_base + p * 16) * ST + ks * 16 + kB_off) * 2;
                    uint32_t bh0, bh1, bh2, bh3, bl0, bl1, bl2, bl3;
                    ldsm4(b2base + eb, bh0, bh1, bh2, bh3);
                    ldsm4(b2base + (uint32_t)(N2 * ST * 2) + eb, bl0, bl1, bl2, bl3);
                    #pragma unroll
                    for (int mt = 0; mt < 2; mt++) {
                        float* c0 = acc2[mt][2 * p];
                        float* c1 = acc2[mt][2 * p + 1];
                        mma_bf16(c0, ah[mt], bh0, bh1);
                        mma_bf16(c0, ah[mt], bl0, bl1);
                        mma_bf16(c0, al[mt], bh0, bh1);
                        mma_bf16(c1, ah[mt], bh2, bh3);
                        mma_bf16(c1, ah[mt], bl2, bl3);
                        mma_bf16(c1, al[mt], bh2, bh3);
                    }
                }
            }
            __syncthreads();
        }

        #pragma unroll
        for (int mt = 0; mt < 2; mt++) {
            #pragma unroll
            for (int half = 0; half < 2; half++) {
                int r = blockRow + m0 + mt * 16 + g + half * 8;
                if (r >= M) continue;
                #pragma unroll
                for (int nt = 0; nt < NT2; nt++) {
                    int cc = n0b + nt * 8 + 2 * t;
                    float v0 = silu_f(acc2[mt][nt][half * 2 + 0]);
                    float v1 = silu_f(acc2[mt][nt][half * 2 + 1]);
                    float2 o; o.x = v0; o.y = v1;
                    *(float2*)(out2 + (size_t)r * N2 + cc) = o;
                }
            }
        }
    }
}

// ---------------- triplet via mma: 2 edges per warp ----------------
// D(16x64) = [cbf_e0(8x16); cbf_e1(8x16)] @ Wc(16x64), bf16 split-3.
// X[e][c] = INV_SQRT_NB * sum_nb T[b1[e][nb]][c] * D[8*esel+nb][c]
__global__ void __launch_bounds__(256)
triplet_mma(const float* __restrict__ T, const float* __restrict__ cbf,
            const int* __restrict__ idx_s, const int* __restrict__ basis,
            const float* __restrict__ Wc,
            __nv_bfloat16* __restrict__ Xh, __nv_bfloat16* __restrict__ Xl, int E)
{
    const int warp = threadIdx.x >> 5;
    const int lane = threadIdx.x & 31;
    const int g = lane >> 2, t = lane & 3;

    // Preload Wc fragments (constant): wb[nt][0] = Wc[2t,2t+1][nt*8+g], wb[nt][1] = Wc[2t+8,2t+9][..]
    uint32_t wbh[8][2], wbl[8][2];
    #pragma unroll
    for (int nt = 0; nt < 8; nt++) {
        int col = nt * 8 + g;
        float c0 = Wc[(2 * t)     * 64 + col];
        float c1 = Wc[(2 * t + 1) * 64 + col];
        float c2 = Wc[(2 * t + 8) * 64 + col];
        float c3 = Wc[(2 * t + 9) * 64 + col];
        split_pack(make_float2(c0, c1), wbh[nt][0], wbl[nt][0]);
        split_pack(make_float2(c2, c3), wbh[nt][1], wbl[nt][1]);
    }

    const float2* cb2 = (const float2*)cbf;
    const float2* T2  = (const float2*)T;

    const int gw = blockIdx.x * 8 + warp;
    const int stride = gridDim.x * 8;

    for (int e0 = gw * 2; e0 < E; e0 += stride * 2) {
        int e1 = e0 + 1;
        bool has1 = (e1 < E);
        int e1c = has1 ? e1 : e0;

        int s0 = idx_s[e0];
        int s1 = idx_s[e1c];
        int bA = __ldg(basis + s0 * 8 + g);
        int bB = __ldg(basis + s1 * 8 + g);

        // A fragments: rows 0-7 = e0 (nb=g), rows 8-15 = e1 (nb=g)
        float2 a0 = cb2[(size_t)e0  * 64 + g * 8 + t];       // (e0,g, c=2t,2t+1)
        float2 a1 = cb2[(size_t)e1c * 64 + g * 8 + t];       // (e1,g, c=2t,2t+1)
        float2 a2 = cb2[(size_t)e0  * 64 + g * 8 + t + 4];   // (e0,g, c=2t+8,+9)
        float2 a3 = cb2[(size_t)e1c * 64 + g * 8 + t + 4];   // (e1,g, c=2t+8,+9)
        uint32_t Af[4], Lf[4];
        split_pack(a0, Af[0], Lf[0]);
        split_pack(a1, Af[1], Lf[1]);
        split_pack(a2, Af[2], Lf[2]);
        split_pack(a3, Af[3], Lf[3]);

        float acc[8][4];
        #pragma unroll
        for (int nt = 0; nt < 8; nt++) {
            acc[nt][0] = acc[nt][1] = acc[nt][2] = acc[nt][3] = 0.f;
            mma_bf16(acc[nt], Af, wbh[nt][0], wbh[nt][1]);
            mma_bf16(acc[nt], Af, wbl[nt][0], wbl[nt][1]);
            mma_bf16(acc[nt], Lf, wbh[nt][0], wbh[nt][1]);
        }

        // T-weight + reduce over nb (= g = lane bits 2..4) + store
        #pragma unroll
        for (int nt = 0; nt < 8; nt++) {
            float2 tA = T2[(size_t)bA * 32 + nt * 4 + t];
            float2 tB = T2[(size_t)bB * 32 + nt * 4 + t];
            float p0 = tA.x * acc[nt][0];
            float p1 = tA.y * acc[nt][1];
            float p2 = tB.x * acc[nt][2];
            float p3 = tB.y * acc[nt][3];
            #pragma unroll
            for (int m = 4; m <= 16; m <<= 1) {
                p0 += __shfl_xor_sync(0xffffffffu, p0, m);
                p1 += __shfl_xor_sync(0xffffffffu, p1, m);
                p2 += __shfl_xor_sync(0xffffffffu, p2, m);
                p3 += __shfl_xor_sync(0xffffffffu, p3, m);
            }
            if (g == 0) {
                uint32_t H, L;
                split_pack(make_float2(p0 * INV_SQRT_NB, p1 * INV_SQRT_NB), H, L);
                size_t i0 = (size_t)e0 * 32 + nt * 4 + t;
                ((uint32_t*)Xh)[i0] = H;
                ((uint32_t*)Xl)[i0] = L;
                if (has1) {
                    split_pack(make_float2(p2 * INV_SQRT_NB, p3 * INV_SQRT_NB), H, L);
                    size_t i1 = (size_t)e1 * 32 + nt * 4 + t;
                    ((uint32_t*)Xh)[i1] = H;
                    ((uint32_t*)Xl)[i1] = L;
                }
            }
        }
    }
}

extern "C" void kernel_launch(void* const* d_in, const int* in_sizes, int n_in,
                              void* d_out, int out_size)
{
    const float* m_st     = (const float*)d_in[0];
    const float* rbf      = (const float*)d_in[1];
    const float* cbf      = (const float*)d_in[2];
    const int*   idx_s    = (const int*)d_in[3];
    const int*   idx_swap = (const int*)d_in[4];
    const int*   basis    = (const int*)d_in[5];
    const float* W_m_rbf  = (const float*)d_in[6];
    const float* W_rbf    = (const float*)d_in[7];
    const float* W_m_cbf  = (const float*)d_in[8];
    const float* W_cbf    = (const float*)d_in[9];
    const float* W_dir    = (const float*)d_in[10];
    const float* W_st     = (const float*)d_in[11];
    const float* W_ts     = (const float*)d_in[12];
    float* out = (float*)d_out;

    const int E = in_sizes[0] / DEDGE;

    float *pT, *pZ;
    __nv_bfloat16 *pmh, *pml, *pXh, *pXl, *pYh, *pYl;
    __nv_bfloat16 *wmrh, *wmrl, *wmch, *wmcl, *wdh, *wdl, *wsth, *wstl, *wtsh, *wtsl;
    cudaGetSymbolAddress((void**)&pT,   g_T);
    cudaGetSymbolAddress((void**)&pZ,   g_Z);
    cudaGetSymbolAddress((void**)&pmh,  g_msth);  cudaGetSymbolAddress((void**)&pml, g_mstl);
    cudaGetSymbolAddress((void**)&pXh,  g_Xh);    cudaGetSymbolAddress((void**)&pXl, g_Xl);
    cudaGetSymbolAddress((void**)&pYh,  g_Yh);    cudaGetSymbolAddress((void**)&pYl, g_Yl);
    cudaGetSymbolAddress((void**)&wmrh, g_Wmrh);  cudaGetSymbolAddress((void**)&wmrl, g_Wmrl);
    cudaGetSymbolAddress((void**)&wmch, g_Wmch);  cudaGetSymbolAddress((void**)&wmcl, g_Wmcl);
    cudaGetSymbolAddress((void**)&wdh,  g_Wdh);   cudaGetSymbolAddress((void**)&wdl, g_Wdl);
    cudaGetSymbolAddress((void**)&wsth, g_Wsth);  cudaGetSymbolAddress((void**)&wstl, g_Wstl);
    cudaGetSymbolAddress((void**)&wtsh, g_Wtsh);  cudaGetSymbolAddress((void**)&wtsl, g_Wtsl);

    const int gB = (E + 127) / 128;

    const int smem_std   = 2 * (2 * 128 * 40 + 2 * 128 * 40) * 2;  // 81920
    const int smem_f12   = 81920 + 2 * 64  * 40 * 2 + 8192;        // 100352
    const int smem_f45   = 81920 + 2 * 128 * 40 * 2;               // 102400

    cudaFuncSetAttribute(gemm_std<128, 128, EPI_FINAL>,
                         cudaFuncAttributeMaxDynamicSharedMemorySize, smem_std);
    cudaFuncSetAttribute(gemm_chain<128, 64, true, false>,
                         cudaFuncAttributeMaxDynamicSharedMemorySize, smem_f12);
    cudaFuncSetAttribute(gemm_chain<64, 128, false, true>,
                         cudaFuncAttributeMaxDynamicSharedMemorySize, smem_f45);

    // ---- setup: split weights (transposed) + m_st ----
    split_w_t<<<(128 * 128 + 255) / 256, 256>>>(W_m_rbf, wmrh, wmrl, 128, 128);
    split_w_t<<<(128 * 64 + 255) / 256, 256>>>(W_m_cbf,  wmch, wmcl, 128, 64);
    split_w_t<<<(64 * 128 + 255) / 256, 256>>>(W_dir,    wdh, wdl, 64, 128);
    split_w_t<<<(128 * 128 + 255) / 256, 256>>>(W_st,    wsth, wstl, 128, 128);
    split_w_t<<<(128 * 128 + 255) / 256, 256>>>(W_ts,    wtsh, wtsl, 128, 128);
    split_rows<<<(E * 64 + 255) / 256, 256>>>(m_st, pmh, pml, E * 64);

    // F12: M1 = silu(m_st @ W_m_rbf) * (rbf @ W_rbf)  (smem)  ->  T = silu(M1 @ W_m_cbf)
    gemm_chain<128, 64, true, false><<<gB, 256, smem_f12>>>(
        pmh, pml, wmrh, wmrl, rbf, W_rbf, wmch, wmcl, pT, nullptr, nullptr, E);
    // K3: triplet (mma) -> X bf16 hi/lo
    triplet_mma<<<2048, 256>>>(pT, cbf, idx_s, basis, W_cbf, pXh, pXl, E);
    // F45: Y = silu(X @ W_dir) (smem + gmem)  ->  Z = silu(Y @ W_ts)
    gemm_chain<64, 128, false, true><<<gB, 256, smem_f45>>>(
        pXh, pXl, wdh, wdl, nullptr, nullptr, wtsh, wtsl, pZ, pYh, pYl, E);
    // K5a (fused final): out = (silu(Y @ W_st) + Z[idx_swap]) * INV_SQRT_2
    gemm_std<128, 128, EPI_FINAL><<<gB, 256, smem_std>>>(
        pYh, pYl, wsth, wstl, out, pZ, idx_swap, E);
}

// round 9
// speedup vs baseline: 1.1448x; 1.1448x over previous
#include <cuda_runtime.h>
#include <cuda_bf16.h>
#include <cuda_fp16.h>
#include <cstdint>
#include <math.h>

#define EMAX   250000
#define DEDGE  128
#define DTRI   64

// fp16 intermediates (gather-heavy -> keep small)
static __device__ __align__(16) __half g_T [EMAX * DTRI];
static __device__ __align__(16) __half g_Z [EMAX * DEDGE];
// bf16 hi/lo pre-split activations
static __device__ __align__(16) __nv_bfloat16 g_msth[EMAX * DEDGE];
static __device__ __align__(16) __nv_bfloat16 g_mstl[EMAX * DEDGE];
static __device__ __align__(16) __nv_bfloat16 g_Xh  [EMAX * DTRI];
static __device__ __align__(16) __nv_bfloat16 g_Xl  [EMAX * DTRI];
static __device__ __align__(16) __nv_bfloat16 g_Yh  [EMAX * DEDGE];
static __device__ __align__(16) __nv_bfloat16 g_Yl  [EMAX * DEDGE];
// bf16 hi/lo transposed weights [N][K]
static __device__ __align__(16) __nv_bfloat16 g_Wmrh [128 * 128], g_Wmrl [128 * 128];
static __device__ __align__(16) __nv_bfloat16 g_Wmch [64 * 128],  g_Wmcl [64 * 128];
static __device__ __align__(16) __nv_bfloat16 g_Wdh  [128 * 64],  g_Wdl  [128 * 64];
static __device__ __align__(16) __nv_bfloat16 g_Wsth [128 * 128], g_Wstl [128 * 128];
static __device__ __align__(16) __nv_bfloat16 g_Wtsh [128 * 128], g_Wtsl [128 * 128];

#define INV_SQRT_2  0.70710678118654752440f
#define INV_SQRT_NB 0.35355339059327376220f

__device__ __forceinline__ float silu_f(float x) {
    return x / (1.0f + __expf(-x));
}
__device__ __forceinline__ uint32_t smem_u32(const void* p) {
    uint32_t a;
    asm("{ .reg .u64 t; cvta.to.shared.u64 t, %1; cvt.u32.u64 %0, t; }" : "=r"(a) : "l"(p));
    return a;
}
__device__ __forceinline__ void cp_async16(uint32_t dst, const void* src, bool v) {
    int sz = v ? 16 : 0;
    asm volatile("cp.async.cg.shared.global [%0], [%1], 16, %2;"
                 :: "r"(dst), "l"(src), "r"(sz));
}
#define CP_COMMIT() asm volatile("cp.async.commit_group;" ::: "memory")
template<int n> __device__ __forceinline__ void cp_wait() {
    asm volatile("cp.async.wait_group %0;" :: "n"(n) : "memory");
}
__device__ __forceinline__ void ldsm4(uint32_t addr, uint32_t& r0, uint32_t& r1,
                                      uint32_t& r2, uint32_t& r3) {
    asm volatile("ldmatrix.sync.aligned.m8n8.x4.shared.b16 {%0,%1,%2,%3}, [%4];"
                 : "=r"(r0), "=r"(r1), "=r"(r2), "=r"(r3) : "r"(addr));
}
__device__ __forceinline__ void mma_bf16(float* c, const uint32_t* a,
                                         uint32_t b0, uint32_t b1) {
    asm volatile(
        "mma.sync.aligned.m16n8k16.row.col.f32.bf16.bf16.f32 "
        "{%0,%1,%2,%3}, {%4,%5,%6,%7}, {%8,%9}, {%0,%1,%2,%3};"
        : "+f"(c[0]), "+f"(c[1]), "+f"(c[2]), "+f"(c[3])
        : "r"(a[0]), "r"(a[1]), "r"(a[2]), "r"(a[3]), "r"(b0), "r"(b1));
}
__device__ __forceinline__ void split1(float v, __nv_bfloat16& h, __nv_bfloat16& l) {
    h = __float2bfloat16(v);
    l = __float2bfloat16(v - __bfloat162float(h));
}
__device__ __forceinline__ uint32_t pack2(__nv_bfloat16 a, __nv_bfloat16 b) {
    __nv_bfloat162 p; p.x = a; p.y = b;
    return *(uint32_t*)&p;
}
__device__ __forceinline__ void split_pack(float2 v, uint32_t& H, uint32_t& L) {
    __nv_bfloat16 hx, lx, hy, ly;
    split1(v.x, hx, lx); split1(v.y, hy, ly);
    H = pack2(hx, hy); L = pack2(lx, ly);
}

// ---------------- setup split kernels ----------------
__global__ void split_rows(const float* __restrict__ src,
                           __nv_bfloat16* __restrict__ dh,
                           __nv_bfloat16* __restrict__ dl, int n2)
{
    int i = blockIdx.x * blockDim.x + threadIdx.x;
    if (i >= n2) return;
    float2 v = ((const float2*)src)[i];
    uint32_t H, L;
    split_pack(v, H, L);
    ((uint32_t*)dh)[i] = H;
    ((uint32_t*)dl)[i] = L;
}

// All 5 weight transpose-splits in one launch (blockIdx.y selects weight)
__global__ void split_w_all(
    const float* __restrict__ s0, __nv_bfloat16* __restrict__ d0h, __nv_bfloat16* __restrict__ d0l,
    const float* __restrict__ s1, __nv_bfloat16* __restrict__ d1h, __nv_bfloat16* __restrict__ d1l,
    const float* __restrict__ s2, __nv_bfloat16* __restrict__ d2h, __nv_bfloat16* __restrict__ d2l,
    const float* __restrict__ s3, __nv_bfloat16* __restrict__ d3h, __nv_bfloat16* __restrict__ d3l,
    const float* __restrict__ s4, __nv_bfloat16* __restrict__ d4h, __nv_bfloat16* __restrict__ d4l)
{
    int i = blockIdx.x * blockDim.x + threadIdx.x;
    int w = blockIdx.y;
    const float* src; __nv_bfloat16 *dh, *dl; int K, N;
    switch (w) {
        case 0: src = s0; dh = d0h; dl = d0l; K = 128; N = 128; break;
        case 1: src = s1; dh = d1h; dl = d1l; K = 128; N = 64;  break;
        case 2: src = s2; dh = d2h; dl = d2l; K = 64;  N = 128; break;
        case 3: src = s3; dh = d3h; dl = d3l; K = 128; N = 128; break;
        default: src = s4; dh = d4h; dl = d4l; K = 128; N = 128; break;
    }
    if (i >= K * N) return;
    int k = i / N, n = i % N;
    __nv_bfloat16 h, l;
    split1(src[i], h, l);
    dh[n * K + k] = h;
    dl[n * K + k] = l;
}

#define EPI_NONE 0
#define EPI_FINAL 3

// ---------------- standalone GEMM (K5a: fused final) ----------------
template<int K, int N, int EPI>
__global__ void __launch_bounds__(256, 2)
gemm_std(const __nv_bfloat16* __restrict__ Ah, const __nv_bfloat16* __restrict__ Al,
         const __nv_bfloat16* __restrict__ Bh, const __nv_bfloat16* __restrict__ Bl,
         float* __restrict__ outf,
         const __half* __restrict__ Zg, const int* __restrict__ swp, int M)
{
    constexpr int NT    = N / 16;
    constexpr int NPAIR = NT / 2;
    constexpr int NCH   = (K + 31) / 32;
    constexpr int ST    = 40;
    constexpr uint32_t OFF_AL = 128 * ST * 2;
    constexpr uint32_t OFF_BH = 2 * 128 * ST * 2;
    constexpr uint32_t OFF_BL = OFF_BH + N * ST * 2;
    constexpr uint32_t SSZ    = OFF_BH + 2 * N * ST * 2;

    extern __shared__ __align__(16) char smu[];
    const uint32_t sbase = smem_u32(smu);

    const int tid  = threadIdx.x;
    const int warp = tid >> 5, lane = tid & 31;
    const int g = lane >> 2, t = lane & 3;
    const int warpM = warp & 3, warpN = warp >> 2;
    const int m0 = warpM * 32;
    const int n0 = warpN * (N / 2);
    const int blockRow = blockIdx.x * 128;

    const int lr  = lane & 7;
    const int rowA_base = m0 + lr + ((lane >> 3) & 1) * 8;
    const int kA_off    = (lane >> 4) * 8;
    const int rowB_base = n0 + lr + (lane >> 4) * 8;
    const int kB_off    = ((lane >> 3) & 1) * 8;

    float acc[2][NT][4];
    #pragma unroll
    for (int mt = 0; mt < 2; mt++)
        #pragma unroll
        for (int nt = 0; nt < NT; nt++)
            #pragma unroll
            for (int j = 0; j < 4; j++) acc[mt][nt][j] = 0.0f;

    auto load_chunk = [&](int kb, int stage) {
        const int k0 = kb * 32;
        const uint32_t sb = sbase + (uint32_t)stage * SSZ;
        #pragma unroll
        for (int j = 0; j < 2; j++) {
            int gg = tid + j * 256;
            int row = gg >> 2, q = gg & 3;
            bool v = (blockRow + row < M) && (k0 + q * 8 < K);
            size_t so = (size_t)(blockRow + row) * K + k0 + q * 8;
            uint32_t d = sb + (uint32_t)(row * ST + q * 8) * 2;
            cp_async16(d, v ? (Ah + so) : Ah, v);
            cp_async16(d + OFF_AL, v ? (Al + so) : Al, v);
        }
        #pragma unroll
        for (int j = 0; j < (N * 4) / 256; j++) {
            int gg = tid + j * 256;
            int n = gg >> 2, q = gg & 3;
            bool v = (k0 + q * 8 < K);
            size_t so = (size_t)n * K + k0 + q * 8;
            uint32_t d = sb + OFF_BH + (uint32_t)(n * ST + q * 8) * 2;
            cp_async16(d, v ? (Bh + so) : Bh, v);
            cp_async16(d + (uint32_t)(N * ST * 2), v ? (Bl + so) : Bl, v);
        }
        CP_COMMIT();
    };

    load_chunk(0, 0);
    for (int kb = 0; kb < NCH; kb++) {
        if (kb + 1 < NCH) { load_chunk(kb + 1, (kb + 1) & 1); cp_wait<1>(); }
        else              { cp_wait<0>(); }
        __syncthreads();

        const uint32_t sb = sbase + (uint32_t)(kb & 1) * SSZ;
        #pragma unroll
        for (int ks = 0; ks < 2; ks++) {
            uint32_t ah[2][4], al[2][4];
            #pragma unroll
            for (int mt = 0; mt < 2; mt++) {
                uint32_t ea = (uint32_t)((rowA_base + mt * 16) * ST + ks * 16 + kA_off) * 2;
                ldsm4(sb + ea,          ah[mt][0], ah[mt][1], ah[mt][2], ah[mt][3]);
                ldsm4(sb + OFF_AL + ea, al[mt][0], al[mt][1], al[mt][2], al[mt][3]);
            }
            #pragma unroll
            for (int p = 0; p < NPAIR; p++) {
                uint32_t eb = (uint32_t)((rowB_base + p * 16) * ST + ks * 16 + kB_off) * 2;
                uint32_t bh0, bh1, bh2, bh3, bl0, bl1, bl2, bl3;
                ldsm4(sb + OFF_BH + eb, bh0, bh1, bh2, bh3);
                ldsm4(sb + OFF_BL + eb, bl0, bl1, bl2, bl3);
                #pragma unroll
                for (int mt = 0; mt < 2; mt++) {
                    float* c0 = acc[mt][2 * p];
                    float* c1 = acc[mt][2 * p + 1];
                    mma_bf16(c0, ah[mt], bh0, bh1);
                    mma_bf16(c0, ah[mt], bl0, bl1);
                    mma_bf16(c0, al[mt], bh0, bh1);
                    mma_bf16(c1, ah[mt], bh2, bh3);
                    mma_bf16(c1, ah[mt], bl2, bl3);
                    mma_bf16(c1, al[mt], bh2, bh3);
                }
            }
        }
        __syncthreads();
    }

    const __half2* Z2 = (const __half2*)Zg;
    #pragma unroll
    for (int mt = 0; mt < 2; mt++) {
        #pragma unroll
        for (int half = 0; half < 2; half++) {
            int r = blockRow + m0 + mt * 16 + g + half * 8;
            if (r >= M) continue;
            int s = 0;
            if (EPI == EPI_FINAL) s = swp[r];
            #pragma unroll
            for (int nt = 0; nt < NT; nt++) {
                int cc = n0 + nt * 8 + 2 * t;
                float v0 = acc[mt][nt][half * 2 + 0];
                float v1 = acc[mt][nt][half * 2 + 1];
                if (EPI != EPI_NONE) { v0 = silu_f(v0); v1 = silu_f(v1); }
                if (EPI == EPI_FINAL) {
                    float2 z = __half22float2(Z2[(size_t)s * (N / 2) + (cc >> 1)]);
                    v0 = (v0 + z.x) * INV_SQRT_2;
                    v1 = (v1 + z.y) * INV_SQRT_2;
                }
                float2 o; o.x = v0; o.y = v1;
                *(float2*)(outf + (size_t)r * N + cc) = o;
            }
        }
    }
}

// ---------------- chained GEMM ----------------
// Phase1: P = silu(A @ B1^T) [* R(rbf@Wrbf fp32 in epilogue)] -> smem slabs (+ optional gmem Y)
// Phase2: out2(fp16) = silu(P @ B2^T)
template<int K1, int N2, bool HAS_R, bool STORE_Y>
__global__ void __launch_bounds__(256, 2)
gemm_chain(const __nv_bfloat16* __restrict__ Ah, const __nv_bfloat16* __restrict__ Al,
           const __nv_bfloat16* __restrict__ B1h, const __nv_bfloat16* __restrict__ B1l,
           const float* __restrict__ rbf_g, const float* __restrict__ Wrbf_g,
           const __nv_bfloat16* __restrict__ B2h, const __nv_bfloat16* __restrict__ B2l,
           __half* __restrict__ out2,
           __nv_bfloat16* __restrict__ Yh, __nv_bfloat16* __restrict__ Yl, int M)
{
    constexpr int N1  = 128;
    constexpr int ST  = 40;
    constexpr int NCH1 = (K1 + 31) / 32;
    constexpr uint32_t OFF_AL = 128 * ST * 2;
    constexpr uint32_t OFF_BH = 2 * 128 * ST * 2;
    constexpr uint32_t SSZ    = OFF_BH + 2 * N1 * ST * 2;   // 40960
    constexpr uint32_t SLAB   = 128 * ST * 2 * 2;           // 20480
    constexpr uint32_t B2OFF  = 2 * SSZ;                    // 81920
    constexpr uint32_t WOFF   = B2OFF + 2u * N2 * ST * 2;
    constexpr int NT2   = N2 / 16;
    constexpr int NPAIR2 = NT2 / 2;

    extern __shared__ __align__(16) char smu[];
    const uint32_t sbase = smem_u32(smu);

    const int tid  = threadIdx.x;
    const int warp = tid >> 5, lane = tid & 31;
    const int g = lane >> 2, t = lane & 3;
    const int warpM = warp & 3, warpN = warp >> 2;
    const int m0 = warpM * 32;
    const int n0 = warpN * 64;
    const int n0b = warpN * (N2 / 2);
    const int blockRow = blockIdx.x * 128;

    const int lr  = lane & 7;
    const int rowA_base = m0 + lr + ((lane >> 3) & 1) * 8;
    const int kA_off    = (lane >> 4) * 8;
    const int rowB_base = n0 + lr + (lane >> 4) * 8;
    const int rowB2_base = n0b + lr + (lane >> 4) * 8;
    const int kB_off    = ((lane >> 3) & 1) * 8;

    // ======== phase 1 ========
    {
        float acc[2][8][4];
        #pragma unroll
        for (int mt = 0; mt < 2; mt++)
            #pragma unroll
            for (int nt = 0; nt < 8; nt++)
                #pragma unroll
                for (int j = 0; j < 4; j++) acc[mt][nt][j] = 0.0f;

        auto load_chunk = [&](int kb, int stage) {
            const int k0 = kb * 32;
            const uint32_t sb = sbase + (uint32_t)stage * SSZ;
            #pragma unroll
            for (int j = 0; j < 2; j++) {
                int gg = tid + j * 256;
                int row = gg >> 2, q = gg & 3;
                bool v = (blockRow + row < M) && (k0 + q * 8 < K1);
                size_t so = (size_t)(blockRow + row) * K1 + k0 + q * 8;
                uint32_t d = sb + (uint32_t)(row * ST + q * 8) * 2;
                cp_async16(d, v ? (Ah + so) : Ah, v);
                cp_async16(d + OFF_AL, v ? (Al + so) : Al, v);
            }
            #pragma unroll
            for (int j = 0; j < 2; j++) {
                int gg = tid + j * 256;
                int n = gg >> 2, q = gg & 3;
                bool v = (k0 + q * 8 < K1);
                size_t so = (size_t)n * K1 + k0 + q * 8;
                uint32_t d = sb + OFF_BH + (uint32_t)(n * ST + q * 8) * 2;
                cp_async16(d, v ? (B1h + so) : B1h, v);
                cp_async16(d + (uint32_t)(N1 * ST * 2), v ? (B1l + so) : B1l, v);
            }
            CP_COMMIT();
        };

        if (HAS_R) {
            #pragma unroll
            for (int j = 0; j < 2; j++) {
                int q = tid + j * 256;
                cp_async16(sbase + WOFF + (uint32_t)q * 16, Wrbf_g + q * 4, true);
            }
        }
        load_chunk(0, 0);
        for (int kb = 0; kb < NCH1; kb++) {
            if (kb + 1 < NCH1) { load_chunk(kb + 1, (kb + 1) & 1); cp_wait<1>(); }
            else               { cp_wait<0>(); }
            __syncthreads();

            const uint32_t sb = sbase + (uint32_t)(kb & 1) * SSZ;
            #pragma unroll
            for (int ks = 0; ks < 2; ks++) {
                uint32_t ah[2][4], al[2][4];
                #pragma unroll
                for (int mt = 0; mt < 2; mt++) {
                    uint32_t ea = (uint32_t)((rowA_base + mt * 16) * ST + ks * 16 + kA_off) * 2;
                    ldsm4(sb + ea,          ah[mt][0], ah[mt][1], ah[mt][2], ah[mt][3]);
                    ldsm4(sb + OFF_AL + ea, al[mt][0], al[mt][1], al[mt][2], al[mt][3]);
                }
                #pragma unroll
                for (int p = 0; p < 4; p++) {
                    uint32_t eb = (uint32_t)((rowB_base + p * 16) * ST + ks * 16 + kB_off) * 2;
                    uint32_t bh0, bh1, bh2, bh3, bl0, bl1, bl2, bl3;
                    ldsm4(sb + OFF_BH + eb, bh0, bh1, bh2, bh3);
                    ldsm4(sb + OFF_BH + (uint32_t)(N1 * ST * 2) + eb, bl0, bl1, bl2, bl3);
                    #pragma unroll
                    for (int mt = 0; mt < 2; mt++) {
                        float* c0 = acc[mt][2 * p];
                        float* c1 = acc[mt][2 * p + 1];
                        mma_bf16(c0, ah[mt], bh0, bh1);
                        mma_bf16(c0, ah[mt], bl0, bl1);
                        mma_bf16(c0, al[mt], bh0, bh1);
                        mma_bf16(c1, ah[mt], bh2, bh3);
                        mma_bf16(c1, ah[mt], bl2, bl3);
                        mma_bf16(c1, al[mt], bh2, bh3);
                    }
                }
            }
            __syncthreads();
        }

        // epilogue 1
        const float2* Wsm2 = (const float2*)(smu + WOFF);
        #pragma unroll
        for (int mt = 0; mt < 2; mt++) {
            int row0 = m0 + mt * 16 + g;
            int row1 = row0 + 8;
            int gr0 = blockRow + row0, gr1 = blockRow + row1;
            float rb0[16], rb1[16];
            if (HAS_R) {
                #pragma unroll
                for (int q = 0; q < 4; q++) {
                    float4 v0 = make_float4(0.f, 0.f, 0.f, 0.f);
                    float4 v1 = make_float4(0.f, 0.f, 0.f, 0.f);
                    if (gr0 < M) v0 = *(const float4*)(rbf_g + (size_t)gr0 * 16 + q * 4);
                    if (gr1 < M) v1 = *(const float4*)(rbf_g + (size_t)gr1 * 16 + q * 4);
                    rb0[q * 4 + 0] = v0.x; rb0[q * 4 + 1] = v0.y;
                    rb0[q * 4 + 2] = v0.z; rb0[q * 4 + 3] = v0.w;
                    rb1[q * 4 + 0] = v1.x; rb1[q * 4 + 1] = v1.y;
                    rb1[q * 4 + 2] = v1.z; rb1[q * 4 + 3] = v1.w;
                }
            }
            #pragma unroll
            for (int nt = 0; nt < 8; nt++) {
                int cc = n0 + nt * 8 + 2 * t;
                float r00 = 1.f, r01 = 1.f, r10 = 1.f, r11 = 1.f;
                if (HAS_R) {
                    r00 = r01 = r10 = r11 = 0.f;
                    #pragma unroll
                    for (int k = 0; k < 16; k++) {
                        float2 w = Wsm2[k * 64 + (cc >> 1)];
                        r00 = fmaf(rb0[k], w.x, r00); r01 = fmaf(rb0[k], w.y, r01);
                        r10 = fmaf(rb1[k], w.x, r10); r11 = fmaf(rb1[k], w.y, r11);
                    }
                }
                float v00 = silu_f(acc[mt][nt][0]) * r00;
                float v01 = silu_f(acc[mt][nt][1]) * r01;
                float v10 = silu_f(acc[mt][nt][2]) * r10;
                float v11 = silu_f(acc[mt][nt][3]) * r11;
                if (gr0 >= M) { v00 = 0.f; v01 = 0.f; }
                if (gr1 >= M) { v10 = 0.f; v11 = 0.f; }
                uint32_t H0, L0, H1, L1;
                split_pack(make_float2(v00, v01), H0, L0);
                split_pack(make_float2(v10, v11), H1, L1);
                uint32_t chunk = (uint32_t)(cc >> 5);
                uint32_t off0 = (uint32_t)(row0 * ST + (cc & 31)) * 2;
                uint32_t off1 = (uint32_t)(row1 * ST + (cc & 31)) * 2;
                *(uint32_t*)(smu + chunk * SLAB + off0)          = H0;
                *(uint32_t*)(smu + chunk * SLAB + OFF_AL + off0) = L0;
                *(uint32_t*)(smu + chunk * SLAB + off1)          = H1;
                *(uint32_t*)(smu + chunk * SLAB + OFF_AL + off1) = L1;
                if (STORE_Y) {
                    if (gr0 < M) {
                        *(uint32_t*)(Yh + (size_t)gr0 * N1 + cc) = H0;
                        *(uint32_t*)(Yl + (size_t)gr0 * N1 + cc) = L0;
                    }
                    if (gr1 < M) {
                        *(uint32_t*)(Yh + (size_t)gr1 * N1 + cc) = H1;
                        *(uint32_t*)(Yl + (size_t)gr1 * N1 + cc) = L1;
                    }
                }
            }
        }
        __syncthreads();
    }

    // ======== phase 2: out2 = silu(P @ B2^T) fp16, K2 = 128 ========
    {
        float acc2[2][NT2][4];
        #pragma unroll
        for (int mt = 0; mt < 2; mt++)
            #pragma unroll
            for (int nt = 0; nt < NT2; nt++)
                #pragma unroll
                for (int j = 0; j < 4; j++) acc2[mt][nt][j] = 0.0f;

        const uint32_t b2base = sbase + B2OFF;

        for (int kb = 0; kb < 4; kb++) {
            #pragma unroll
            for (int j = 0; j < (N2 * 4) / 256; j++) {
                int gg = tid + j * 256;
                int n = gg >> 2, q = gg & 3;
                size_t so = (size_t)n * 128 + kb * 32 + q * 8;
                uint32_t d = b2base + (uint32_t)(n * ST + q * 8) * 2;
                cp_async16(d, B2h + so, true);
                cp_async16(d + (uint32_t)(N2 * ST * 2), B2l + so, true);
            }
            CP_COMMIT();
            cp_wait<0>();
            __syncthreads();

            const uint32_t slab = sbase + (uint32_t)kb * SLAB;
            #pragma unroll
            for (int ks = 0; ks < 2; ks++) {
                uint32_t ah[2][4], al[2][4];
                #pragma unroll
                for (int mt = 0; mt < 2; mt++) {
                    uint32_t ea = (uint32_t)((rowA_base + mt * 16) * ST + ks * 16 + kA_off) * 2;
                    ldsm4(slab + ea,          ah[mt][0], ah[mt][1], ah[mt][2], ah[mt][3]);
                    ldsm4(slab + OFF_AL + ea, al[mt][0], al[mt][1], al[mt][2], al[mt][3]);
                }
                #pragma unroll
                for (int p = 0; p < NPAIR2; p++) {
                    uint32_t eb = (uint32_t)((rowB2_base + p * 16) * ST + ks * 16 + kB_off) * 2;
                    uint32_t bh0, bh1, bh2, bh3, bl0, bl1, bl2, bl3;
                    ldsm4(b2base + eb, bh0, bh1, bh2, bh3);
                    ldsm4(b2base + (uint32_t)(N2 * ST * 2) + eb, bl0, bl1, bl2, bl3);
                    #pragma unroll
                    for (int mt = 0; mt < 2; mt++) {
                        float* c0 = acc2[mt][2 * p];
                        float* c1 = acc2[mt][2 * p + 1];
                        mma_bf16(c0, ah[mt], bh0, bh1);
                        mma_bf16(c0, ah[mt], bl0, bl1);
                        mma_bf16(c0, al[mt], bh0, bh1);
                        mma_bf16(c1, ah[mt], bh2, bh3);
                        mma_bf16(c1, ah[mt], bl2, bl3);
                        mma_bf16(c1, al[mt], bh2, bh3);
                    }
                }
            }
            __syncthreads();
        }

        #pragma unroll
        for (int mt = 0; mt < 2; mt++) {
            #pragma unroll
            for (int half = 0; half < 2; half++) {
                int r = blockRow + m0 + mt * 16 + g + half * 8;
                if (r >= M) continue;
                #pragma unroll
                for (int nt = 0; nt < NT2; nt++) {
                    int cc = n0b + nt * 8 + 2 * t;
                    float v0 = silu_f(acc2[mt][nt][half * 2 + 0]);
                    float v1 = silu_f(acc2[mt][nt][half * 2 + 1]);
                    ((__half2*)out2)[(size_t)r * (N2 / 2) + (cc >> 1)] =
                        __floats2half2_rn(v0, v1);
                }
            }
        }
    }
}

// ---------------- triplet (FFMA, fp16 T, half2 columns) ----------------
// X[e][2l,2l+1] = INV_SQRT_NB * sum_nb T[b1[e,nb]][2l,2l+1] * (cbf[e,nb,:] @ W_cbf[:,2l,2l+1])
__global__ void __launch_bounds__(256)
triplet_kernel(const __half* __restrict__ T, const float* __restrict__ cbf,
               const int* __restrict__ idx_s, const int* __restrict__ basis,
               const float* __restrict__ Wc,
               __nv_bfloat16* __restrict__ Xh, __nv_bfloat16* __restrict__ Xl, int E)
{
    __shared__ float cb[8][128];
    const int warp = threadIdx.x >> 5;
    const int lane = threadIdx.x & 31;

    float w0[16], w1[16];
    #pragma unroll
    for (int c = 0; c < 16; c++) {
        w0[c] = Wc[c * 64 + 2 * lane];
        w1[c] = Wc[c * 64 + 2 * lane + 1];
    }

    const __half2* T2 = (const __half2*)T;
    const int gw = blockIdx.x * 8 + warp;
    const int nwarps = gridDim.x * 8;

    for (int e = gw; e < E; e += nwarps) {
        int s = idx_s[e];
        int b1v = 0;
        if (lane < 8) b1v = basis[s * 8 + lane];

        float4 v = *(const float4*)(cbf + (size_t)e * 128 + lane * 4);
        *(float4*)(&cb[warp][lane * 4]) = v;
        __syncwarp();

        int bidx[8];
        #pragma unroll
        for (int nb = 0; nb < 8; nb++)
            bidx[nb] = __shfl_sync(0xffffffffu, b1v, nb);

        __half2 tv[8];
        #pragma unroll
        for (int nb = 0; nb < 8; nb++)
            tv[nb] = T2[(size_t)bidx[nb] * 32 + lane];

        float acc0 = 0.f, acc1 = 0.f;
        #pragma unroll
        for (int nb = 0; nb < 8; nb++) {
            float d0 = 0.f, d1 = 0.f;
            #pragma unroll
            for (int c = 0; c < 16; c++) {
                float a = cb[warp][nb * 16 + c];
                d0 = fmaf(a, w0[c], d0);
                d1 = fmaf(a, w1[c], d1);
            }
            float2 tt = __half22float2(tv[nb]);
            acc0 = fmaf(tt.x, d0, acc0);
            acc1 = fmaf(tt.y, d1, acc1);
        }
        uint32_t H, L;
        split_pack(make_float2(acc0 * INV_SQRT_NB, acc1 * INV_SQRT_NB), H, L);
        ((uint32_t*)Xh)[(size_t)e * 32 + lane] = H;
        ((uint32_t*)Xl)[(size_t)e * 32 + lane] = L;
        __syncwarp();
    }
}

extern "C" void kernel_launch(void* const* d_in, const int* in_sizes, int n_in,
                              void* d_out, int out_size)
{
    const float* m_st     = (const float*)d_in[0];
    const float* rbf      = (const float*)d_in[1];
    const float* cbf      = (const float*)d_in[2];
    const int*   idx_s    = (const int*)d_in[3];
    const int*   idx_swap = (const int*)d_in[4];
    const int*   basis    = (const int*)d_in[5];
    const float* W_m_rbf  = (const float*)d_in[6];
    const float* W_rbf    = (const float*)d_in[7];
    const float* W_m_cbf  = (const float*)d_in[8];
    const float* W_cbf    = (const float*)d_in[9];
    const float* W_dir    = (const float*)d_in[10];
    const float* W_st     = (const float*)d_in[11];
    const float* W_ts     = (const float*)d_in[12];
    float* out = (float*)d_out;

    const int E = in_sizes[0] / DEDGE;

    __half *pT, *pZ;
    __nv_bfloat16 *pmh, *pml, *pXh, *pXl, *pYh, *pYl;
    __nv_bfloat16 *wmrh, *wmrl, *wmch, *wmcl, *wdh, *wdl, *wsth, *wstl, *wtsh, *wtsl;
    cudaGetSymbolAddress((void**)&pT,   g_T);
    cudaGetSymbolAddress((void**)&pZ,   g_Z);
    cudaGetSymbolAddress((void**)&pmh,  g_msth);  cudaGetSymbolAddress((void**)&pml, g_mstl);
    cudaGetSymbolAddress((void**)&pXh,  g_Xh);    cudaGetSymbolAddress((void**)&pXl, g_Xl);
    cudaGetSymbolAddress((void**)&pYh,  g_Yh);    cudaGetSymbolAddress((void**)&pYl, g_Yl);
    cudaGetSymbolAddress((void**)&wmrh, g_Wmrh);  cudaGetSymbolAddress((void**)&wmrl, g_Wmrl);
    cudaGetSymbolAddress((void**)&wmch, g_Wmch);  cudaGetSymbolAddress((void**)&wmcl, g_Wmcl);
    cudaGetSymbolAddress((void**)&wdh,  g_Wdh);   cudaGetSymbolAddress((void**)&wdl, g_Wdl);
    cudaGetSymbolAddress((void**)&wsth, g_Wsth);  cudaGetSymbolAddress((void**)&wstl, g_Wstl);
    cudaGetSymbolAddress((void**)&wtsh, g_Wtsh);  cudaGetSymbolAddress((void**)&wtsl, g_Wtsl);

    const int gB = (E + 127) / 128;

    const int smem_std   = 2 * (2 * 128 * 40 + 2 * 128 * 40) * 2;  // 81920
    const int smem_f12   = 81920 + 2 * 64  * 40 * 2 + 8192;        // 100352
    const int smem_f45   = 81920 + 2 * 128 * 40 * 2;               // 102400

    cudaFuncSetAttribute(gemm_std<128, 128, EPI_FINAL>,
                         cudaFuncAttributeMaxDynamicSharedMemorySize, smem_std);
    cudaFuncSetAttribute(gemm_chain<128, 64, true, false>,
                         cudaFuncAttributeMaxDynamicSharedMemorySize, smem_f12);
    cudaFuncSetAttribute(gemm_chain<64, 128, false, true>,
                         cudaFuncAttributeMaxDynamicSharedMemorySize, smem_f45);

    // launch 0: split m_st
    split_rows<<<(E * 64 + 255) / 256, 256>>>(m_st, pmh, pml, E * 64);
    // launch 1: split all 5 weights
    {
        dim3 grid(64, 5);
        split_w_all<<<grid, 256>>>(
            W_m_rbf, wmrh, wmrl,
            W_m_cbf, wmch, wmcl,
            W_dir,   wdh,  wdl,
            W_st,    wsth, wstl,
            W_ts,    wtsh, wtsl);
    }
    // launch 2 (F12): M1 = silu(m_st @ W_m_rbf) * (rbf @ W_rbf) -> T(fp16) = silu(M1 @ W_m_cbf)
    gemm_chain<128, 64, true, false><<<gB, 256, smem_f12>>>(
        pmh, pml, wmrh, wmrl, rbf, W_rbf, wmch, wmcl, pT, nullptr, nullptr, E);
    // launch 3: triplet -> X bf16 hi/lo
    triplet_kernel<<<2048, 256>>>(pT, cbf, idx_s, basis, W_cbf, pXh, pXl, E);
    // launch 4 (F45): Y = silu(X @ W_dir) (smem+gmem) -> Z(fp16) = silu(Y @ W_ts)
    gemm_chain<64, 128, false, true><<<gB, 256, smem_f45>>>(
        pXh, pXl, wdh, wdl, nullptr, nullptr, wtsh, wtsl, pZ, pYh, pYl, E);
    // launch 5 (K5a, fused final): out = (silu(Y @ W_st) + Z[idx_swap]) * INV_SQRT_2
    gemm_std<128, 128, EPI_FINAL><<<gB, 256, smem_std>>>(
        pYh, pYl, wsth, wstl, out, pZ, idx_swap, E);
}

// round 10
// speedup vs baseline: 1.1848x; 1.0349x over previous
#include <cuda_runtime.h>
#include <cuda_bf16.h>
#include <cuda_fp16.h>
#include <cstdint>
#include <math.h>

#define EMAX   250000
#define DEDGE  128
#define DTRI   64

// fp16 intermediates (gather-heavy / round-trip -> keep small)
static __device__ __align__(16) __half g_T  [EMAX * DTRI];
static __device__ __align__(16) __half g_Z  [EMAX * DEDGE];
static __device__ __align__(16) __half g_XST[EMAX * DEDGE];
// bf16 hi/lo pre-split activations
static __device__ __align__(16) __nv_bfloat16 g_msth[EMAX * DEDGE];
static __device__ __align__(16) __nv_bfloat16 g_mstl[EMAX * DEDGE];
static __device__ __align__(16) __nv_bfloat16 g_Xh  [EMAX * DTRI];
static __device__ __align__(16) __nv_bfloat16 g_Xl  [EMAX * DTRI];
// bf16 hi/lo transposed weights [N][K]
static __device__ __align__(16) __nv_bfloat16 g_Wmrh [128 * 128], g_Wmrl [128 * 128];
static __device__ __align__(16) __nv_bfloat16 g_Wmch [64 * 128],  g_Wmcl [64 * 128];
static __device__ __align__(16) __nv_bfloat16 g_Wdh  [128 * 64],  g_Wdl  [128 * 64];
static __device__ __align__(16) __nv_bfloat16 g_Wsth [128 * 128], g_Wstl [128 * 128];
static __device__ __align__(16) __nv_bfloat16 g_Wtsh [128 * 128], g_Wtsl [128 * 128];

#define INV_SQRT_2  0.70710678118654752440f
#define INV_SQRT_NB 0.35355339059327376220f

__device__ __forceinline__ float silu_f(float x) {
    return x / (1.0f + __expf(-x));
}
__device__ __forceinline__ uint32_t smem_u32(const void* p) {
    uint32_t a;
    asm("{ .reg .u64 t; cvta.to.shared.u64 t, %1; cvt.u32.u64 %0, t; }" : "=r"(a) : "l"(p));
    return a;
}
__device__ __forceinline__ void cp_async16(uint32_t dst, const void* src, bool v) {
    int sz = v ? 16 : 0;
    asm volatile("cp.async.cg.shared.global [%0], [%1], 16, %2;"
                 :: "r"(dst), "l"(src), "r"(sz));
}
#define CP_COMMIT() asm volatile("cp.async.commit_group;" ::: "memory")
template<int n> __device__ __forceinline__ void cp_wait() {
    asm volatile("cp.async.wait_group %0;" :: "n"(n) : "memory");
}
__device__ __forceinline__ void ldsm4(uint32_t addr, uint32_t& r0, uint32_t& r1,
                                      uint32_t& r2, uint32_t& r3) {
    asm volatile("ldmatrix.sync.aligned.m8n8.x4.shared.b16 {%0,%1,%2,%3}, [%4];"
                 : "=r"(r0), "=r"(r1), "=r"(r2), "=r"(r3) : "r"(addr));
}
__device__ __forceinline__ void mma_bf16(float* c, const uint32_t* a,
                                         uint32_t b0, uint32_t b1) {
    asm volatile(
        "mma.sync.aligned.m16n8k16.row.col.f32.bf16.bf16.f32 "
        "{%0,%1,%2,%3}, {%4,%5,%6,%7}, {%8,%9}, {%0,%1,%2,%3};"
        : "+f"(c[0]), "+f"(c[1]), "+f"(c[2]), "+f"(c[3])
        : "r"(a[0]), "r"(a[1]), "r"(a[2]), "r"(a[3]), "r"(b0), "r"(b1));
}
__device__ __forceinline__ void split1(float v, __nv_bfloat16& h, __nv_bfloat16& l) {
    h = __float2bfloat16(v);
    l = __float2bfloat16(v - __bfloat162float(h));
}
__device__ __forceinline__ uint32_t pack2(__nv_bfloat16 a, __nv_bfloat16 b) {
    __nv_bfloat162 p; p.x = a; p.y = b;
    return *(uint32_t*)&p;
}
__device__ __forceinline__ void split_pack(float2 v, uint32_t& H, uint32_t& L) {
    __nv_bfloat16 hx, lx, hy, ly;
    split1(v.x, hx, lx); split1(v.y, hy, ly);
    H = pack2(hx, hy); L = pack2(lx, ly);
}

// ---------------- setup split kernels ----------------
__global__ void split_rows(const float* __restrict__ src,
                           __nv_bfloat16* __restrict__ dh,
                           __nv_bfloat16* __restrict__ dl, int n2)
{
    int i = blockIdx.x * blockDim.x + threadIdx.x;
    if (i >= n2) return;
    float2 v = ((const float2*)src)[i];
    uint32_t H, L;
    split_pack(v, H, L);
    ((uint32_t*)dh)[i] = H;
    ((uint32_t*)dl)[i] = L;
}

__global__ void split_w_all(
    const float* __restrict__ s0, __nv_bfloat16* __restrict__ d0h, __nv_bfloat16* __restrict__ d0l,
    const float* __restrict__ s1, __nv_bfloat16* __restrict__ d1h, __nv_bfloat16* __restrict__ d1l,
    const float* __restrict__ s2, __nv_bfloat16* __restrict__ d2h, __nv_bfloat16* __restrict__ d2l,
    const float* __restrict__ s3, __nv_bfloat16* __restrict__ d3h, __nv_bfloat16* __restrict__ d3l,
    const float* __restrict__ s4, __nv_bfloat16* __restrict__ d4h, __nv_bfloat16* __restrict__ d4l)
{
    int i = blockIdx.x * blockDim.x + threadIdx.x;
    int w = blockIdx.y;
    const float* src; __nv_bfloat16 *dh, *dl; int K, N;
    switch (w) {
        case 0: src = s0; dh = d0h; dl = d0l; K = 128; N = 128; break;
        case 1: src = s1; dh = d1h; dl = d1l; K = 128; N = 64;  break;
        case 2: src = s2; dh = d2h; dl = d2l; K = 64;  N = 128; break;
        case 3: src = s3; dh = d3h; dl = d3l; K = 128; N = 128; break;
        default: src = s4; dh = d4h; dl = d4l; K = 128; N = 128; break;
    }
    if (i >= K * N) return;
    int k = i / N, n = i % N;
    __nv_bfloat16 h, l;
    split1(src[i], h, l);
    dh[n * K + k] = h;
    dl[n * K + k] = l;
}

// ---------------- chained GEMM (2 or 3 phases) ----------------
// Phase1: P = silu(A @ B1^T) [* R(rbf@Wrbf fp32 in epilogue)] -> smem slabs
// Phase2: out2(fp16) = silu(P @ B2^T)
// Phase3 (if THREE): out3(fp16) = silu(P @ B3^T)
template<int K1, int N2, bool HAS_R, bool THREE>
__global__ void __launch_bounds__(256, 2)
gemm_chain(const __nv_bfloat16* __restrict__ Ah, const __nv_bfloat16* __restrict__ Al,
           const __nv_bfloat16* __restrict__ B1h, const __nv_bfloat16* __restrict__ B1l,
           const float* __restrict__ rbf_g, const float* __restrict__ Wrbf_g,
           const __nv_bfloat16* __restrict__ B2h, const __nv_bfloat16* __restrict__ B2l,
           __half* __restrict__ out2,
           const __nv_bfloat16* __restrict__ B3h, const __nv_bfloat16* __restrict__ B3l,
           __half* __restrict__ out3, int M)
{
    constexpr int N1  = 128;
    constexpr int ST  = 40;
    constexpr int NCH1 = (K1 + 31) / 32;
    constexpr uint32_t OFF_AL = 128 * ST * 2;
    constexpr uint32_t OFF_BH = 2 * 128 * ST * 2;
    constexpr uint32_t SSZ    = OFF_BH + 2 * N1 * ST * 2;   // 40960
    constexpr uint32_t SLAB   = 128 * ST * 2 * 2;           // 20480
    constexpr uint32_t B2OFF  = 2 * SSZ;                    // 81920
    constexpr uint32_t WOFF   = B2OFF + 2u * N2 * ST * 2;
    constexpr int NT2   = N2 / 16;
    constexpr int NPAIR2 = NT2 / 2;

    extern __shared__ __align__(16) char smu[];
    const uint32_t sbase = smem_u32(smu);

    const int tid  = threadIdx.x;
    const int warp = tid >> 5, lane = tid & 31;
    const int g = lane >> 2, t = lane & 3;
    const int warpM = warp & 3, warpN = warp >> 2;
    const int m0 = warpM * 32;
    const int n0 = warpN * 64;
    const int n0b = warpN * (N2 / 2);
    const int blockRow = blockIdx.x * 128;

    const int lr  = lane & 7;
    const int rowA_base = m0 + lr + ((lane >> 3) & 1) * 8;
    const int kA_off    = (lane >> 4) * 8;
    const int rowB_base = n0 + lr + (lane >> 4) * 8;
    const int rowB2_base = n0b + lr + (lane >> 4) * 8;
    const int kB_off    = ((lane >> 3) & 1) * 8;

    // ======== phase 1 ========
    {
        float acc[2][8][4];
        #pragma unroll
        for (int mt = 0; mt < 2; mt++)
            #pragma unroll
            for (int nt = 0; nt < 8; nt++)
                #pragma unroll
                for (int j = 0; j < 4; j++) acc[mt][nt][j] = 0.0f;

        auto load_chunk = [&](int kb, int stage) {
            const int k0 = kb * 32;
            const uint32_t sb = sbase + (uint32_t)stage * SSZ;
            #pragma unroll
            for (int j = 0; j < 2; j++) {
                int gg = tid + j * 256;
                int row = gg >> 2, q = gg & 3;
                bool v = (blockRow + row < M) && (k0 + q * 8 < K1);
                size_t so = (size_t)(blockRow + row) * K1 + k0 + q * 8;
                uint32_t d = sb + (uint32_t)(row * ST + q * 8) * 2;
                cp_async16(d, v ? (Ah + so) : Ah, v);
                cp_async16(d + OFF_AL, v ? (Al + so) : Al, v);
            }
            #pragma unroll
            for (int j = 0; j < 2; j++) {
                int gg = tid + j * 256;
                int n = gg >> 2, q = gg & 3;
                bool v = (k0 + q * 8 < K1);
                size_t so = (size_t)n * K1 + k0 + q * 8;
                uint32_t d = sb + OFF_BH + (uint32_t)(n * ST + q * 8) * 2;
                cp_async16(d, v ? (B1h + so) : B1h, v);
                cp_async16(d + (uint32_t)(N1 * ST * 2), v ? (B1l + so) : B1l, v);
            }
            CP_COMMIT();
        };

        if (HAS_R) {
            #pragma unroll
            for (int j = 0; j < 2; j++) {
                int q = tid + j * 256;
                cp_async16(sbase + WOFF + (uint32_t)q * 16, Wrbf_g + q * 4, true);
            }
        }
        load_chunk(0, 0);
        for (int kb = 0; kb < NCH1; kb++) {
            if (kb + 1 < NCH1) { load_chunk(kb + 1, (kb + 1) & 1); cp_wait<1>(); }
            else               { cp_wait<0>(); }
            __syncthreads();

            const uint32_t sb = sbase + (uint32_t)(kb & 1) * SSZ;
            #pragma unroll
            for (int ks = 0; ks < 2; ks++) {
                uint32_t ah[2][4], al[2][4];
                #pragma unroll
                for (int mt = 0; mt < 2; mt++) {
                    uint32_t ea = (uint32_t)((rowA_base + mt * 16) * ST + ks * 16 + kA_off) * 2;
                    ldsm4(sb + ea,          ah[mt][0], ah[mt][1], ah[mt][2], ah[mt][3]);
                    ldsm4(sb + OFF_AL + ea, al[mt][0], al[mt][1], al[mt][2], al[mt][3]);
                }
                #pragma unroll
                for (int p = 0; p < 4; p++) {
                    uint32_t eb = (uint32_t)((rowB_base + p * 16) * ST + ks * 16 + kB_off) * 2;
                    uint32_t bh0, bh1, bh2, bh3, bl0, bl1, bl2, bl3;
                    ldsm4(sb + OFF_BH + eb, bh0, bh1, bh2, bh3);
                    ldsm4(sb + OFF_BH + (uint32_t)(N1 * ST * 2) + eb, bl0, bl1, bl2, bl3);
                    #pragma unroll
                    for (int mt = 0; mt < 2; mt++) {
                        float* c0 = acc[mt][2 * p];
                        float* c1 = acc[mt][2 * p + 1];
                        mma_bf16(c0, ah[mt], bh0, bh1);
                        mma_bf16(c0, ah[mt], bl0, bl1);
                        mma_bf16(c0, al[mt], bh0, bh1);
                        mma_bf16(c1, ah[mt], bh2, bh3);
                        mma_bf16(c1, ah[mt], bl2, bl3);
                        mma_bf16(c1, al[mt], bh2, bh3);
                    }
                }
            }
            __syncthreads();
        }

        // epilogue 1: silu [* R], split -> slabs
        const float2* Wsm2 = (const float2*)(smu + WOFF);
        #pragma unroll
        for (int mt = 0; mt < 2; mt++) {
            int row0 = m0 + mt * 16 + g;
            int row1 = row0 + 8;
            int gr0 = blockRow + row0, gr1 = blockRow + row1;
            float rb0[16], rb1[16];
            if (HAS_R) {
                #pragma unroll
                for (int q = 0; q < 4; q++) {
                    float4 v0 = make_float4(0.f, 0.f, 0.f, 0.f);
                    float4 v1 = make_float4(0.f, 0.f, 0.f, 0.f);
                    if (gr0 < M) v0 = *(const float4*)(rbf_g + (size_t)gr0 * 16 + q * 4);
                    if (gr1 < M) v1 = *(const float4*)(rbf_g + (size_t)gr1 * 16 + q * 4);
                    rb0[q * 4 + 0] = v0.x; rb0[q * 4 + 1] = v0.y;
                    rb0[q * 4 + 2] = v0.z; rb0[q * 4 + 3] = v0.w;
                    rb1[q * 4 + 0] = v1.x; rb1[q * 4 + 1] = v1.y;
                    rb1[q * 4 + 2] = v1.z; rb1[q * 4 + 3] = v1.w;
                }
            }
            #pragma unroll
            for (int nt = 0; nt < 8; nt++) {
                int cc = n0 + nt * 8 + 2 * t;
                float r00 = 1.f, r01 = 1.f, r10 = 1.f, r11 = 1.f;
                if (HAS_R) {
                    r00 = r01 = r10 = r11 = 0.f;
                    #pragma unroll
                    for (int k = 0; k < 16; k++) {
                        float2 w = Wsm2[k * 64 + (cc >> 1)];
                        r00 = fmaf(rb0[k], w.x, r00); r01 = fmaf(rb0[k], w.y, r01);
                        r10 = fmaf(rb1[k], w.x, r10); r11 = fmaf(rb1[k], w.y, r11);
                    }
                }
                float v00 = silu_f(acc[mt][nt][0]) * r00;
                float v01 = silu_f(acc[mt][nt][1]) * r01;
                float v10 = silu_f(acc[mt][nt][2]) * r10;
                float v11 = silu_f(acc[mt][nt][3]) * r11;
                if (gr0 >= M) { v00 = 0.f; v01 = 0.f; }
                if (gr1 >= M) { v10 = 0.f; v11 = 0.f; }
                uint32_t H0, L0, H1, L1;
                split_pack(make_float2(v00, v01), H0, L0);
                split_pack(make_float2(v10, v11), H1, L1);
                uint32_t chunk = (uint32_t)(cc >> 5);
                uint32_t off0 = (uint32_t)(row0 * ST + (cc & 31)) * 2;
                uint32_t off1 = (uint32_t)(row1 * ST + (cc & 31)) * 2;
                *(uint32_t*)(smu + chunk * SLAB + off0)          = H0;
                *(uint32_t*)(smu + chunk * SLAB + OFF_AL + off0) = L0;
                *(uint32_t*)(smu + chunk * SLAB + off1)          = H1;
                *(uint32_t*)(smu + chunk * SLAB + OFF_AL + off1) = L1;
            }
        }
        __syncthreads();
    }

    // ======== phase 2 (+3): silu(P @ B^T) -> fp16, K = 128 ========
    const uint32_t b2base = sbase + B2OFF;
    #pragma unroll
    for (int ph = 0; ph < (THREE ? 2 : 1); ph++) {
        const __nv_bfloat16* Bh = (ph == 0) ? B2h : B3h;
        const __nv_bfloat16* Bl = (ph == 0) ? B2l : B3l;
        __half* outp = (ph == 0) ? out2 : out3;

        float acc2[2][NT2][4];
        #pragma unroll
        for (int mt = 0; mt < 2; mt++)
            #pragma unroll
            for (int nt = 0; nt < NT2; nt++)
                #pragma unroll
                for (int j = 0; j < 4; j++) acc2[mt][nt][j] = 0.0f;

        for (int kb = 0; kb < 4; kb++) {
            #pragma unroll
            for (int j = 0; j < (N2 * 4) / 256; j++) {
                int gg = tid + j * 256;
                int n = gg >> 2, q = gg & 3;
                size_t so = (size_t)n * 128 + kb * 32 + q * 8;
                uint32_t d = b2base + (uint32_t)(n * ST + q * 8) * 2;
                cp_async16(d, Bh + so, true);
                cp_async16(d + (uint32_t)(N2 * ST * 2), Bl + so, true);
            }
            CP_COMMIT();
            cp_wait<0>();
            __syncthreads();

            const uint32_t slab = sbase + (uint32_t)kb * SLAB;
            #pragma unroll
            for (int ks = 0; ks < 2; ks++) {
                uint32_t ah[2][4], al[2][4];
                #pragma unroll
                for (int mt = 0; mt < 2; mt++) {
                    uint32_t ea = (uint32_t)((rowA_base + mt * 16) * ST + ks * 16 + kA_off) * 2;
                    ldsm4(slab + ea,          ah[mt][0], ah[mt][1], ah[mt][2], ah[mt][3]);
                    ldsm4(slab + OFF_AL + ea, al[mt][0], al[mt][1], al[mt][2], al[mt][3]);
                }
                #pragma unroll
                for (int p = 0; p < NPAIR2; p++) {
                    uint32_t eb = (uint32_t)((rowB2_base + p * 16) * ST + ks * 16 + kB_off) * 2;
                    uint32_t bh0, bh1, bh2, bh3, bl0, bl1, bl2, bl3;
                    ldsm4(b2base + eb, bh0, bh1, bh2, bh3);
                    ldsm4(b2base + (uint32_t)(N2 * ST * 2) + eb, bl0, bl1, bl2, bl3);
                    #pragma unroll
                    for (int mt = 0; mt < 2; mt++) {
                        float* c0 = acc2[mt][2 * p];
                        float* c1 = acc2[mt][2 * p + 1];
                        mma_bf16(c0, ah[mt], bh0, bh1);
                        mma_bf16(c0, ah[mt], bl0, bl1);
                        mma_bf16(c0, al[mt], bh0, bh1);
                        mma_bf16(c1, ah[mt], bh2, bh3);
                        mma_bf16(c1, ah[mt], bl2, bl3);
                        mma_bf16(c1, al[mt], bh2, bh3);
                    }
                }
            }
            __syncthreads();
        }

        #pragma unroll
        for (int mt = 0; mt < 2; mt++) {
            #pragma unroll
            for (int half = 0; half < 2; half++) {
                int r = blockRow + m0 + mt * 16 + g + half * 8;
                if (r >= M) continue;
                #pragma unroll
                for (int nt = 0; nt < NT2; nt++) {
                    int cc = n0b + nt * 8 + 2 * t;
                    float v0 = silu_f(acc2[mt][nt][half * 2 + 0]);
                    float v1 = silu_f(acc2[mt][nt][half * 2 + 1]);
                    ((__half2*)outp)[(size_t)r * (N2 / 2) + (cc >> 1)] =
                        __floats2half2_rn(v0, v1);
                }
            }
        }
        if (THREE && ph == 0) __syncthreads();
    }
}

// ---------------- triplet (FFMA, fp16 T) ----------------
__global__ void __launch_bounds__(256)
triplet_kernel(const __half* __restrict__ T, const float* __restrict__ cbf,
               const int* __restrict__ idx_s, const int* __restrict__ basis,
               const float* __restrict__ Wc,
               __nv_bfloat16* __restrict__ Xh, __nv_bfloat16* __restrict__ Xl, int E)
{
    __shared__ float cb[8][128];
    const int warp = threadIdx.x >> 5;
    const int lane = threadIdx.x & 31;

    float w0[16], w1[16];
    #pragma unroll
    for (int c = 0; c < 16; c++) {
        w0[c] = Wc[c * 64 + 2 * lane];
        w1[c] = Wc[c * 64 + 2 * lane + 1];
    }

    const __half2* T2 = (const __half2*)T;
    const int gw = blockIdx.x * 8 + warp;
    const int nwarps = gridDim.x * 8;

    for (int e = gw; e < E; e += nwarps) {
        int s = idx_s[e];
        int b1v = 0;
        if (lane < 8) b1v = basis[s * 8 + lane];

        float4 v = *(const float4*)(cbf + (size_t)e * 128 + lane * 4);
        *(float4*)(&cb[warp][lane * 4]) = v;
        __syncwarp();

        int bidx[8];
        #pragma unroll
        for (int nb = 0; nb < 8; nb++)
            bidx[nb] = __shfl_sync(0xffffffffu, b1v, nb);

        __half2 tv[8];
        #pragma unroll
        for (int nb = 0; nb < 8; nb++)
            tv[nb] = T2[(size_t)bidx[nb] * 32 + lane];

        float acc0 = 0.f, acc1 = 0.f;
        #pragma unroll
        for (int nb = 0; nb < 8; nb++) {
            float d0 = 0.f, d1 = 0.f;
            #pragma unroll
            for (int c = 0; c < 16; c++) {
                float a = cb[warp][nb * 16 + c];
                d0 = fmaf(a, w0[c], d0);
                d1 = fmaf(a, w1[c], d1);
            }
            float2 tt = __half22float2(tv[nb]);
            acc0 = fmaf(tt.x, d0, acc0);
            acc1 = fmaf(tt.y, d1, acc1);
        }
        uint32_t H, L;
        split_pack(make_float2(acc0 * INV_SQRT_NB, acc1 * INV_SQRT_NB), H, L);
        ((uint32_t*)Xh)[(size_t)e * 32 + lane] = H;
        ((uint32_t*)Xl)[(size_t)e * 32 + lane] = L;
        __syncwarp();
    }
}

// ---------------- final elementwise: out = (XST + Z[swap]) * c ----------------
__global__ void __launch_bounds__(256)
final_ew(const __half* __restrict__ XST, const __half* __restrict__ Z,
         const int* __restrict__ swp, float* __restrict__ out, int E)
{
    size_t total = (size_t)E * 16;          // 16 x uint4 (8 halfs) per 128-col row
    size_t stride = (size_t)gridDim.x * blockDim.x;
    for (size_t i = (size_t)blockIdx.x * blockDim.x + threadIdx.x; i < total; i += stride) {
        size_t e = i >> 4;
        int    q = (int)(i & 15);
        int    s = swp[e];
        uint4 a = ((const uint4*)XST)[i];
        uint4 b = ((const uint4*)Z)[(size_t)s * 16 + q];
        const __half2* ah = (const __half2*)&a;
        const __half2* bh = (const __half2*)&b;
        float4 o0, o1;
        float2 r0 = __half22float2(ah[0]), z0 = __half22float2(bh[0]);
        float2 r1 = __half22float2(ah[1]), z1 = __half22float2(bh[1]);
        float2 r2 = __half22float2(ah[2]), z2 = __half22float2(bh[2]);
        float2 r3 = __half22float2(ah[3]), z3 = __half22float2(bh[3]);
        o0.x = (r0.x + z0.x) * INV_SQRT_2; o0.y = (r0.y + z0.y) * INV_SQRT_2;
        o0.z = (r1.x + z1.x) * INV_SQRT_2; o0.w = (r1.y + z1.y) * INV_SQRT_2;
        o1.x = (r2.x + z2.x) * INV_SQRT_2; o1.y = (r2.y + z2.y) * INV_SQRT_2;
        o1.z = (r3.x + z3.x) * INV_SQRT_2; o1.w = (r3.y + z3.y) * INV_SQRT_2;
        ((float4*)out)[e * 32 + q * 2]     = o0;
        ((float4*)out)[e * 32 + q * 2 + 1] = o1;
    }
}

extern "C" void kernel_launch(void* const* d_in, const int* in_sizes, int n_in,
                              void* d_out, int out_size)
{
    const float* m_st     = (const float*)d_in[0];
    const float* rbf      = (const float*)d_in[1];
    const float* cbf      = (const float*)d_in[2];
    const int*   idx_s    = (const int*)d_in[3];
    const int*   idx_swap = (const int*)d_in[4];
    const int*   basis    = (const int*)d_in[5];
    const float* W_m_rbf  = (const float*)d_in[6];
    const float* W_rbf    = (const float*)d_in[7];
    const float* W_m_cbf  = (const float*)d_in[8];
    const float* W_cbf    = (const float*)d_in[9];
    const float* W_dir    = (const float*)d_in[10];
    const float* W_st     = (const float*)d_in[11];
    const float* W_ts     = (const float*)d_in[12];
    float* out = (float*)d_out;

    const int E = in_sizes[0] / DEDGE;

    __half *pT, *pZ, *pXST;
    __nv_bfloat16 *pmh, *pml, *pXh, *pXl;
    __nv_bfloat16 *wmrh, *wmrl, *wmch, *wmcl, *wdh, *wdl, *wsth, *wstl, *wtsh, *wtsl;
    cudaGetSymbolAddress((void**)&pT,   g_T);
    cudaGetSymbolAddress((void**)&pZ,   g_Z);
    cudaGetSymbolAddress((void**)&pXST, g_XST);
    cudaGetSymbolAddress((void**)&pmh,  g_msth);  cudaGetSymbolAddress((void**)&pml, g_mstl);
    cudaGetSymbolAddress((void**)&pXh,  g_Xh);    cudaGetSymbolAddress((void**)&pXl, g_Xl);
    cudaGetSymbolAddress((void**)&wmrh, g_Wmrh);  cudaGetSymbolAddress((void**)&wmrl, g_Wmrl);
    cudaGetSymbolAddress((void**)&wmch, g_Wmch);  cudaGetSymbolAddress((void**)&wmcl, g_Wmcl);
    cudaGetSymbolAddress((void**)&wdh,  g_Wdh);   cudaGetSymbolAddress((void**)&wdl, g_Wdl);
    cudaGetSymbolAddress((void**)&wsth, g_Wsth);  cudaGetSymbolAddress((void**)&wstl, g_Wstl);
    cudaGetSymbolAddress((void**)&wtsh, g_Wtsh);  cudaGetSymbolAddress((void**)&wtsl, g_Wtsl);

    const int gB = (E + 127) / 128;

    const int smem_f12 = 81920 + 2 * 64  * 40 * 2 + 8192;  // 100352
    const int smem_f45 = 81920 + 2 * 128 * 40 * 2;         // 102400

    cudaFuncSetAttribute(gemm_chain<128, 64, true, false>,
                         cudaFuncAttributeMaxDynamicSharedMemorySize, smem_f12);
    cudaFuncSetAttribute(gemm_chain<64, 128, false, true>,
                         cudaFuncAttributeMaxDynamicSharedMemorySize, smem_f45);

    // launch 0: split m_st
    split_rows<<<(E * 64 + 255) / 256, 256>>>(m_st, pmh, pml, E * 64);
    // launch 1: split all 5 weights
    {
        dim3 grid(64, 5);
        split_w_all<<<grid, 256>>>(
            W_m_rbf, wmrh, wmrl,
            W_m_cbf, wmch, wmcl,
            W_dir,   wdh,  wdl,
            W_st,    wsth, wstl,
            W_ts,    wtsh, wtsl);
    }
    // launch 2 (F12): M1 = silu(m_st@W_m_rbf) * (rbf@W_rbf) -> T(fp16) = silu(M1@W_m_cbf)
    gemm_chain<128, 64, true, false><<<gB, 256, smem_f12>>>(
        pmh, pml, wmrh, wmrl, rbf, W_rbf, wmch, wmcl, pT,
        nullptr, nullptr, nullptr, E);
    // launch 3: triplet -> X bf16 hi/lo
    triplet_kernel<<<2048, 256>>>(pT, cbf, idx_s, basis, W_cbf, pXh, pXl, E);
    // launch 4 (F45, 3-phase): Y = silu(X@W_dir) (smem) -> Z(fp16)=silu(Y@W_ts), XST(fp16)=silu(Y@W_st)
    gemm_chain<64, 128, false, true><<<gB, 256, smem_f45>>>(
        pXh, pXl, wdh, wdl, nullptr, nullptr, wtsh, wtsl, pZ,
        wsth, wstl, pXST, E);
    // launch 5: out = (XST + Z[idx_swap]) * INV_SQRT_2
    final_ew<<<4096, 256>>>(pXST, pZ, idx_swap, out, E);
}